// round 10
// baseline (speedup 1.0000x reference)
#include <cuda_runtime.h>

// Problem shape (fixed by the bench)
#define BB 8
#define SS 2048
#define HH 2048

// Scratch (no allocations allowed)
__device__ float g_uv[BB * SS * 4];      // per-row dots: h·W[:H,0], h·W[:H,1], h·W[H:,0], h·W[H:,1]
__device__ float g_v[BB * SS];           // per-input-position weight in transform
__device__ int   g_seg_start[BB * SS];   // first input s for output row t
__device__ int   g_seg_len[BB * SS];     // number of input s for output row t
__device__ int   g_new_len[BB];

// ---------------------------------------------------------------------------
// Kernel A v3: thread tid owns h columns tid*8..tid*8+7 (its 32 W values in
// registers). Hot loop per row is LDG -> 32 FFMA -> ONE STS.128 of the 4
// partials (no shuffles, no result-latency ops, fully pipelined). One barrier
// per 8-row tile; then warp w reduces row w from smem with conflict-free
// LDS.32 (bank == lane) + 3 shuffles.
// ---------------------------------------------------------------------------
__global__ void __launch_bounds__(256) k_dots(const float* __restrict__ h,
                                              const float* __restrict__ W) {
    const int tid = threadIdx.x;
    const float4* Wp = reinterpret_cast<const float4*>(W);   // W: [2H,2] row-major
    const int q0 = tid * 2;                                  // first h-float4 index

    const float4 wa0 = __ldg(Wp + tid * 4 + 0);
    const float4 wa1 = __ldg(Wp + tid * 4 + 1);
    const float4 wa2 = __ldg(Wp + tid * 4 + 2);
    const float4 wa3 = __ldg(Wp + tid * 4 + 3);
    const float4 wb0 = __ldg(Wp + 1024 + tid * 4 + 0);       // second half: rows H+j
    const float4 wb1 = __ldg(Wp + 1024 + tid * 4 + 1);
    const float4 wb2 = __ldg(Wp + 1024 + tid * 4 + 2);
    const float4 wb3 = __ldg(Wp + 1024 + tid * 4 + 3);

    __shared__ float part[8][256][4];                        // 32KB: [row][tid][comp]

    const int row0 = blockIdx.x * 8;
    const float4* hp = reinterpret_cast<const float4*>(h) + (size_t)row0 * (HH / 4);

    float4 h0 = __ldg(hp + q0);
    float4 h1 = __ldg(hp + q0 + 1);

#pragma unroll
    for (int rr = 0; rr < 8; rr++) {
        float4 n0, n1;
        if (rr < 7) {                                        // prefetch next row
            const float4* np = hp + (rr + 1) * (HH / 4);
            n0 = __ldg(np + q0);
            n1 = __ldg(np + q0 + 1);
        }

        float a0 = h0.x * wa0.x + h0.y * wa0.z + h0.z * wa1.x + h0.w * wa1.z
                 + h1.x * wa2.x + h1.y * wa2.z + h1.z * wa3.x + h1.w * wa3.z;
        float a1 = h0.x * wa0.y + h0.y * wa0.w + h0.z * wa1.y + h0.w * wa1.w
                 + h1.x * wa2.y + h1.y * wa2.w + h1.z * wa3.y + h1.w * wa3.w;
        float c0 = h0.x * wb0.x + h0.y * wb0.z + h0.z * wb1.x + h0.w * wb1.z
                 + h1.x * wb2.x + h1.y * wb2.z + h1.z * wb3.x + h1.w * wb3.z;
        float c1 = h0.x * wb0.y + h0.y * wb0.w + h0.z * wb1.y + h0.w * wb1.w
                 + h1.x * wb2.y + h1.y * wb2.w + h1.z * wb3.y + h1.w * wb3.w;

        *reinterpret_cast<float4*>(&part[rr][tid][0]) = make_float4(a0, a1, c0, c1);

        if (rr < 7) { h0 = n0; h1 = n1; }
    }
    __syncthreads();                                         // ONE barrier per tile

    // warp w reduces row w: lane l sums comp (l&3) over tids == (l>>2) mod 8.
    // float index (g+8k)*4 + c has bank ((l>>2)*4 + (l&3)) % 32 == l: conflict-free.
    const int w = tid >> 5, l = tid & 31;
    const int c = l & 3, g = l >> 2;
    float s = 0.f;
#pragma unroll
    for (int k = 0; k < 32; k++) s += part[w][g + 8 * k][c];
    s += __shfl_down_sync(0xffffffffu, s, 16);
    s += __shfl_down_sync(0xffffffffu, s, 8);
    s += __shfl_down_sync(0xffffffffu, s, 4);
    if (l < 4) g_uv[(size_t)(row0 + w) * 4 + l] = s;
}

// ---------------------------------------------------------------------------
// Kernel B: per-batch. logits, gumbel-softmax, mm, want, v, prefix scan of inc,
// segment map, and all small outputs. One 256-thread block per batch.
// ---------------------------------------------------------------------------
__global__ void __launch_bounds__(256) k_scan(const int* __restrict__ amask,
                                              const int* __restrict__ smask,
                                              const float* __restrict__ gum,
                                              const float* __restrict__ bias,
                                              float* __restrict__ out) {
    const int b = blockIdx.x;
    const int tid = threadIdx.x;
    const size_t base = (size_t)b * SS;

    __shared__ unsigned char want_sh[SS];
    __shared__ int r_sh[SS];
    __shared__ int part[256];
    __shared__ int cnt_sh[SS];
    __shared__ int sst_sh[SS];
    __shared__ int sh_T;

    // output layout: tuple members concatenated, all fp32
    float* out_mask    = out + (size_t)BB * SS * HH;
    float* out_special = out_mask + (size_t)BB * SS;
    float* out_counts  = out_special + (size_t)BB * SS;
    float* out_mm      = out_counts + (size_t)BB * SS;
    float* out_logits  = out_mm + (size_t)BB * SS * 2;

    // --- T = sum(attention_mask[b]) ---
    if (tid == 0) sh_T = 0;
    __syncthreads();
    {
        int local = 0;
#pragma unroll
        for (int i = 0; i < 8; i++) local += amask[base + tid * 8 + i];
        atomicAdd(&sh_T, local);
    }
    __syncthreads();
    const int T = sh_T;

    const float b0v = __ldg(bias + 0), b1v = __ldg(bias + 1);

    // --- per-position: logits, gumbel-softmax, mm, want, v ---
#pragma unroll
    for (int i = 0; i < 8; i++) {
        const int s = tid * 8 + i;
        float l0, l1;
        if (s < SS - 1) {
            const float* uvA = g_uv + (base + s) * 4;
            const float* uvB = g_uv + (base + s + 1) * 4;
            l0 = uvA[0] + uvB[2] + b0v;
            l1 = uvA[1] + uvB[3] + b1v;
        } else {                                     // zero stub row
            l0 = b0v; l1 = b1v;
        }
        out_logits[(base + s) * 2 + 0] = l0;
        out_logits[(base + s) * 2 + 1] = l1;

        const float z0 = l0 + gum[(base + s) * 2 + 0];
        const float z1 = l1 + gum[(base + s) * 2 + 1];
        const float m = fmaxf(z0, z1);
        const float e0 = expf(z0 - m), e1 = expf(z1 - m);
        const float inv = 1.f / (e0 + e1);
        const float ys0 = e0 * inv, ys1 = e1 * inv;
        const int idx1 = (ys1 > ys0) ? 1 : 0;        // argmax, ties -> 0 (matches jnp)
        float mm0 = ((idx1 == 0 ? 1.f : 0.f) - ys0) + ys0;   // straight-through, exact fp order
        float mm1 = ((idx1 == 1 ? 1.f : 0.f) - ys1) + ys1;
        if (smask[base + s]) { mm0 = 1.f; mm1 = 0.f; }
        const float mf = amask[base + s] ? 1.f : 0.f;
        mm0 *= mf; mm1 *= mf;
        out_mm[(base + s) * 2 + 0] = mm0;
        out_mm[(base + s) * 2 + 1] = mm1;

        const bool want = (mm1 > 0.5f) && (s >= 1) && (s < T - 1);
        want_sh[s] = want ? 1 : 0;
        float v = want ? mm1 : mm0;
        if (s == 0) v = 1.f;
        if (s >= T) v = 0.f;
        g_v[base + s] = v;
    }
    __syncthreads();

    // --- inc + block prefix scan -> r ---
    int incs[8];
    {
        int csum = 0;
#pragma unroll
        for (int i = 0; i < 8; i++) {
            const int s = tid * 8 + i;
            const int w = want_sh[s];
            const int wp = (s > 0) ? want_sh[s - 1] : 0;
            const int inc = (s < T && s >= 1 && !(w && wp)) ? 1 : 0;
            csum += inc;
            incs[i] = csum;                          // local inclusive
        }
        part[tid] = csum;
    }
    __syncthreads();
    for (int off = 1; off < 256; off <<= 1) {
        const int add = (tid >= off) ? part[tid - off] : 0;
        __syncthreads();
        part[tid] += add;
        __syncthreads();
    }
    {
        const int offset = (tid > 0) ? part[tid - 1] : 0;
#pragma unroll
        for (int i = 0; i < 8; i++) r_sh[tid * 8 + i] = offset + incs[i];
    }
    __syncthreads();

    // --- segment map via shared atomics ---
#pragma unroll
    for (int i = 0; i < 8; i++) { cnt_sh[tid * 8 + i] = 0; sst_sh[tid * 8 + i] = 0x7fffffff; }
    __syncthreads();
#pragma unroll
    for (int i = 0; i < 8; i++) {
        const int s = tid * 8 + i;
        if (s < T) {
            const int r = r_sh[s];
            atomicAdd(&cnt_sh[r], 1);
            atomicMin(&sst_sh[r], s);
        }
    }
    __syncthreads();

    const int nl = r_sh[SS - 1] + 1;                 // matches reference r[:, -1] + 1
#pragma unroll
    for (int i = 0; i < 8; i++) {
        const int t = tid * 8 + i;
        out_mask[base + t]    = (t < nl) ? 1.f : 0.f;
        out_special[base + t] = (t == 0 || t == nl - 1) ? 1.f : 0.f;
        out_counts[base + t]  = (float)cnt_sh[t];
        g_seg_start[base + t] = sst_sh[t];
        g_seg_len[base + t]   = cnt_sh[t];
    }
    if (tid == 0) g_new_len[b] = nl;
}

// ---------------------------------------------------------------------------
// Kernel C v2: 8 output rows per 256-thread block. Consecutive output rows own
// contiguous input runs, so each block streams a contiguous ~10-row span of h.
// Blocks traverse rows DESCENDING (L2 reuse of k_dots' ascending stream);
// output stores are __stcs (evict-first) to protect the h working set.
// ---------------------------------------------------------------------------
__global__ void __launch_bounds__(256) k_merge(const float* __restrict__ h,
                                               float* __restrict__ out) {
    const int blk = (BB * SS / 8 - 1) - blockIdx.x;  // descending traversal
    const int t0 = blk * 8;                          // first global output row
    const int b = t0 >> 11;                          // batch (8 rows never straddle)
    const int tid = threadIdx.x;
    const int q0 = tid * 2;
    const int nl = g_new_len[b];
    const size_t base = (size_t)b * SS;

#pragma unroll
    for (int j = 0; j < 8; j++) {
        const int row = t0 + j;                      // global output row index
        const int t = row & (SS - 1);
        float4 acc0 = make_float4(0.f, 0.f, 0.f, 0.f);
        float4 acc1 = make_float4(0.f, 0.f, 0.f, 0.f);

        if (t < nl) {
            const int s0 = g_seg_start[row];
            const int L  = g_seg_len[row];
            for (int i = 0; i < L; i++) {
                const size_t srow = base + s0 + i;
                const float w = __ldg(g_v + srow);
                const float4* hr = reinterpret_cast<const float4*>(h) + srow * (HH / 4);
                const float4 x0 = __ldg(hr + q0);
                const float4 x1 = __ldg(hr + q0 + 1);
                acc0.x += w * x0.x; acc0.y += w * x0.y; acc0.z += w * x0.z; acc0.w += w * x0.w;
                acc1.x += w * x1.x; acc1.y += w * x1.y; acc1.z += w * x1.z; acc1.w += w * x1.w;
            }
        }
        float4* orow = reinterpret_cast<float4*>(out) + (size_t)row * (HH / 4);
        __stcs(orow + q0,     acc0);
        __stcs(orow + q0 + 1, acc1);
    }
}

// ---------------------------------------------------------------------------
extern "C" void kernel_launch(void* const* d_in, const int* in_sizes, int n_in,
                              void* d_out, int out_size) {
    const float* h     = (const float*)d_in[0];   // [B,S,H] f32
    const int*   amask = (const int*)d_in[1];     // [B,S]   i32
    const int*   smask = (const int*)d_in[2];     // [B,S]   i32
    const float* gum   = (const float*)d_in[3];   // [B,S,2] f32
    const float* W     = (const float*)d_in[4];   // [2H,2]  f32
    const float* bias  = (const float*)d_in[5];   // [2]     f32
    float* out = (float*)d_out;

    k_dots<<<(BB * SS) / 8, 256>>>(h, W);
    k_scan<<<BB, 256>>>(amask, smask, gum, bias, out);
    k_merge<<<(BB * SS) / 8, 256>>>(h, out);
}